// round 4
// baseline (speedup 1.0000x reference)
#include <cuda_runtime.h>

// Problem constants
#define B_   1024
#define T_   512
#define I_   16
#define H_   50
#define G_   200     // 4*H
#define FCD  64
#define NB   7       // batch rows per block -> grid = 147, single wave on 148 SMs
#define NTH  448     // 14 warps: warps 0-6 group A, warps 7-13 group B
#define NC1  (NB * H_)        // 350 L1 cells
#define NCELL (2 * NB * H_)   // 700 cells total

typedef unsigned long long ull;

// ---- f32x2 packed helpers (sm_103a FFMA2) ----
__device__ __forceinline__ void fma2(ull& acc, ull a, ull b) {
    asm("fma.rn.f32x2 %0, %1, %2, %0;" : "+l"(acc) : "l"(a), "l"(b));
}
__device__ __forceinline__ ull pk2(float x, float y) {
    ull r;
    asm("mov.b64 %0, {%1, %2};" : "=l"(r) : "f"(x), "f"(y));
    return r;
}
__device__ __forceinline__ float rsum(ull v) {
    float2 r;
    asm("mov.b64 {%0, %1}, %2;" : "=f"(r.x), "=f"(r.y) : "l"(v));
    return r.x + r.y;
}
__device__ __forceinline__ float sigf(float x) {
    return 1.0f / (1.0f + __expf(-x));
}
__device__ __forceinline__ float tanh_f(float x) {
    return 2.0f / (1.0f + __expf(-2.0f * x)) - 1.0f;
}

// Fused 2-layer LSTM, software-pipelined by one timestep:
//   iteration it: L1 step it (x_it, h1_{it-1});  L2 step it-1 (h1_{it-1}, h2_{it-2})
// Gate work K-split across two warp groups so weights fit registers WITHOUT spills:
//   A: all of L1 (x + h1) + first 8 f32x2-chunks of L2's h1-part  (84 weight regs)
//   B: last 18 chunks of L2's h1-part + all of L2's h2-part       (88 weight regs)
__global__ __launch_bounds__(NTH, 1)
void fused_lstm_kernel(const float* __restrict__ x,
                       const float* __restrict__ w_ih0,  // [G, I]
                       const float* __restrict__ w_hh0,  // [G, H]
                       const float* __restrict__ b_ih0,
                       const float* __restrict__ b_hh0,
                       const float* __restrict__ w_ih1,  // [G, H]
                       const float* __restrict__ w_hh1,  // [G, H]
                       const float* __restrict__ b_ih1,
                       const float* __restrict__ b_hh1,
                       const float* __restrict__ fc1_w,  // [FC, H]
                       const float* __restrict__ fc1_b,
                       const float* __restrict__ fc2_w,  // [1, FC]
                       const float* __restrict__ fc2_b,
                       float* __restrict__ out)          // [B, 1]
{
    __shared__ __align__(16) float x_sh[2][NB][I_];   // double-buffered x tile
    __shared__ __align__(16) float hx[2][NB][52];     // [0]=h1, [1]=h2 (padded)
    __shared__ float gl1[NB][G_];                     // L1 gate pre-activations (full)
    __shared__ float pa[NB][G_];                      // L2 partial from group A
    __shared__ float pb[NB][G_];                      // L2 partial from group B

    const int tid  = threadIdx.x;
    const int row0 = blockIdx.x * NB;
    const bool grpA = (tid < 224);
    const int  g    = grpA ? tid : tid - 224;
    const bool isGate = (g < G_);

    // ---- zero h buffers (pads must stay 0) ----
    for (int i = tid; i < 2 * NB * 52; i += NTH) ((float*)hx)[i] = 0.0f;

    // ---- load weights into registers (f32x2 packed, padded with zeros) ----
    ull wx[8], wh1[26], w2a[8];     // group A
    ull w2b[18], wh2[26];           // group B
    float bias1 = 0.0f, bias2 = 0.0f;
    if (isGate) {
        if (grpA) {
            #pragma unroll
            for (int k2 = 0; k2 < 8; k2++)
                wx[k2] = pk2(__ldg(&w_ih0[g * I_ + 2 * k2]),
                             __ldg(&w_ih0[g * I_ + 2 * k2 + 1]));
            #pragma unroll
            for (int k2 = 0; k2 < 26; k2++) {
                float a0 = (2 * k2     < H_) ? __ldg(&w_hh0[g * H_ + 2 * k2])     : 0.0f;
                float a1 = (2 * k2 + 1 < H_) ? __ldg(&w_hh0[g * H_ + 2 * k2 + 1]) : 0.0f;
                wh1[k2] = pk2(a0, a1);
            }
            #pragma unroll
            for (int k2 = 0; k2 < 8; k2++)
                w2a[k2] = pk2(__ldg(&w_ih1[g * H_ + 2 * k2]),
                              __ldg(&w_ih1[g * H_ + 2 * k2 + 1]));
            bias1 = __ldg(&b_ih0[g]) + __ldg(&b_hh0[g]);
            bias2 = __ldg(&b_ih1[g]) + __ldg(&b_hh1[g]);
        } else {
            #pragma unroll
            for (int k2 = 8; k2 < 26; k2++) {
                float a0 = (2 * k2     < H_) ? __ldg(&w_ih1[g * H_ + 2 * k2])     : 0.0f;
                float a1 = (2 * k2 + 1 < H_) ? __ldg(&w_ih1[g * H_ + 2 * k2 + 1]) : 0.0f;
                w2b[k2 - 8] = pk2(a0, a1);
            }
            #pragma unroll
            for (int k2 = 0; k2 < 26; k2++) {
                float a0 = (2 * k2     < H_) ? __ldg(&w_hh1[g * H_ + 2 * k2])     : 0.0f;
                float a1 = (2 * k2 + 1 < H_) ? __ldg(&w_hh1[g * H_ + 2 * k2 + 1]) : 0.0f;
                wh2[k2] = pk2(a0, a1);
            }
        }
    }

    // ---- combine ownership: cells tid and tid+NTH ----
    float c_st[2] = {0.0f, 0.0f};
    int   cr[2], cj[2];
    bool  cvalid[2], cisl2[2];
    #pragma unroll
    for (int k = 0; k < 2; k++) {
        int cell = tid + k * NTH;
        cvalid[k] = (cell < NCELL);
        int c2 = cvalid[k] ? cell : 0;
        cisl2[k] = (c2 >= NC1);
        int rem = cisl2[k] ? (c2 - NC1) : c2;
        cr[k] = rem / H_;
        cj[k] = rem - cr[k] * H_;
    }

    // ---- prefetch lane mapping: 48 inactive lanes load 112 x elements ----
    const bool isPfLane = !isGate;
    const int  pid = grpA ? (tid - 200) : (24 + (tid - 424));

    // ---- preload x_0 (cooperative) ----
    if (tid < NB * I_) {
        int r = tid / I_, kk = tid - r * I_;
        int gr = min(row0 + r, B_ - 1);
        x_sh[0][r][kk] = x[gr * (T_ * I_) + kk];
    }
    __syncthreads();

    int buf = 0;
    for (int it = 0; it <= T_; it++) {
        // -- prefetch x_{it+1}: LDGs issued up front, hidden under gate math --
        float pv[3];
        const bool doPf = isPfLane && (it + 1 < T_);
        if (doPf) {
            #pragma unroll
            for (int i = 0; i < 3; i++) {
                int e = pid + i * 48;
                if (e < NB * I_) {
                    int r = e / I_, kk = e - r * I_;
                    int gr = min(row0 + r, B_ - 1);
                    pv[i] = x[gr * (T_ * I_) + (it + 1) * I_ + kk];
                }
            }
        }

        // -- gate phase --
        if (isGate) {
            if (grpA) {
                ull a1[NB], a2[NB];
                #pragma unroll
                for (int r = 0; r < NB; r++) {
                    a1[r] = pk2(bias1, 0.0f);
                    a2[r] = pk2(bias2, 0.0f);
                }
                #pragma unroll
                for (int q = 0; q < 4; q++) {        // x part
                    #pragma unroll
                    for (int r = 0; r < NB; r++) {
                        const ulonglong2 v = *(const ulonglong2*)&x_sh[buf][r][4 * q];
                        fma2(a1[r], wx[2 * q],     v.x);
                        fma2(a1[r], wx[2 * q + 1], v.y);
                    }
                }
                #pragma unroll
                for (int q = 0; q < 13; q++) {       // h1 part (feeds a1, and a2 for q<4)
                    #pragma unroll
                    for (int r = 0; r < NB; r++) {
                        const ulonglong2 v = *(const ulonglong2*)&hx[0][r][4 * q];
                        fma2(a1[r], wh1[2 * q],     v.x);
                        fma2(a1[r], wh1[2 * q + 1], v.y);
                        if (q < 4) {
                            fma2(a2[r], w2a[2 * q],     v.x);
                            fma2(a2[r], w2a[2 * q + 1], v.y);
                        }
                    }
                }
                #pragma unroll
                for (int r = 0; r < NB; r++) {
                    gl1[r][g] = rsum(a1[r]);
                    pa[r][g]  = rsum(a2[r]);
                }
            } else {
                ull a2[NB];
                #pragma unroll
                for (int r = 0; r < NB; r++) a2[r] = 0ull;
                #pragma unroll
                for (int q = 4; q < 13; q++) {       // h1 chunks 8..25
                    #pragma unroll
                    for (int r = 0; r < NB; r++) {
                        const ulonglong2 v = *(const ulonglong2*)&hx[0][r][4 * q];
                        fma2(a2[r], w2b[2 * q - 8], v.x);
                        fma2(a2[r], w2b[2 * q - 7], v.y);
                    }
                }
                #pragma unroll
                for (int q = 0; q < 13; q++) {       // h2 part
                    #pragma unroll
                    for (int r = 0; r < NB; r++) {
                        const ulonglong2 v = *(const ulonglong2*)&hx[1][r][4 * q];
                        fma2(a2[r], wh2[2 * q],     v.x);
                        fma2(a2[r], wh2[2 * q + 1], v.y);
                    }
                }
                #pragma unroll
                for (int r = 0; r < NB; r++) pb[r][g] = rsum(a2[r]);
            }
        }
        __syncthreads();

        // -- combine: 1-2 cells per thread (gate order i, f, g, o) --
        #pragma unroll
        for (int k = 0; k < 2; k++) {
            if (cvalid[k]) {
                const bool act = cisl2[k] ? (it >= 1) : (it < T_);
                if (act) {
                    const int r = cr[k], j = cj[k];
                    float gi, gf, gg_, go_;
                    if (cisl2[k]) {
                        gi  = pa[r][j]          + pb[r][j];
                        gf  = pa[r][H_ + j]     + pb[r][H_ + j];
                        gg_ = pa[r][2 * H_ + j] + pb[r][2 * H_ + j];
                        go_ = pa[r][3 * H_ + j] + pb[r][3 * H_ + j];
                    } else {
                        gi  = gl1[r][j];
                        gf  = gl1[r][H_ + j];
                        gg_ = gl1[r][2 * H_ + j];
                        go_ = gl1[r][3 * H_ + j];
                    }
                    float ig = sigf(gi);
                    float fg = sigf(gf);
                    float gv = tanh_f(gg_);
                    float og = sigf(go_);
                    c_st[k] = fg * c_st[k] + ig * gv;
                    hx[cisl2[k] ? 1 : 0][r][j] = og * tanh_f(c_st[k]);
                }
            }
        }
        // commit prefetched x into the other buffer
        if (doPf) {
            #pragma unroll
            for (int i = 0; i < 3; i++) {
                int e = pid + i * 48;
                if (e < NB * I_) {
                    int r = e / I_, kk = e - r * I_;
                    x_sh[buf ^ 1][r][kk] = pv[i];
                }
            }
        }
        __syncthreads();
        buf ^= 1;
    }

    // ---- FC head: warp w handles batch row row0+w, shfl reduction ----
    const int wid  = tid / 32;
    const int lane = tid - wid * 32;
    if (wid < NB) {
        const int row = row0 + wid;
        if (row < B_) {
            float s = 0.0f;
            #pragma unroll
            for (int uu = 0; uu < 2; uu++) {
                const int u = lane + uu * 32;
                float a = __ldg(&fc1_b[u]);
                #pragma unroll
                for (int k = 0; k < H_; k++)
                    a += __ldg(&fc1_w[u * H_ + k]) * hx[1][wid][k];
                a = fmaxf(a, 0.0f);
                s += a * __ldg(&fc2_w[u]);
            }
            #pragma unroll
            for (int off = 16; off > 0; off >>= 1)
                s += __shfl_down_sync(0xffffffffu, s, off);
            if (lane == 0) out[row] = s + __ldg(&fc2_b[0]);
        }
    }
}

extern "C" void kernel_launch(void* const* d_in, const int* in_sizes, int n_in,
                              void* d_out, int out_size) {
    const float* x     = (const float*)d_in[0];
    const float* w_ih0 = (const float*)d_in[1];
    const float* w_hh0 = (const float*)d_in[2];
    const float* b_ih0 = (const float*)d_in[3];
    const float* b_hh0 = (const float*)d_in[4];
    const float* w_ih1 = (const float*)d_in[5];
    const float* w_hh1 = (const float*)d_in[6];
    const float* b_ih1 = (const float*)d_in[7];
    const float* b_hh1 = (const float*)d_in[8];
    const float* fc1_w = (const float*)d_in[9];
    const float* fc1_b = (const float*)d_in[10];
    const float* fc2_w = (const float*)d_in[11];
    const float* fc2_b = (const float*)d_in[12];
    float* out = (float*)d_out;

    const int grid = (B_ + NB - 1) / NB;   // 147
    fused_lstm_kernel<<<grid, NTH>>>(
        x, w_ih0, w_hh0, b_ih0, b_hh0,
        w_ih1, w_hh1, b_ih1, b_hh1,
        fc1_w, fc1_b, fc2_w, fc2_b, out);
}

// round 5
// speedup vs baseline: 1.1061x; 1.1061x over previous
#include <cuda_runtime.h>
#include <cstdint>

// Problem constants
#define B_   1024
#define T_   512
#define I_   16
#define H_   50
#define G_   200      // 4*H
#define FCD  64
#define NB   7        // rows per block -> grid 147, single wave
#define NTH  672      // 21 warps: 3 groups x 7 warps (200 gate threads each)
#define NC1  (NB * H_)        // 350
#define NCELL (2 * NB * H_)   // 700
#define SLAB (NB * G_)        // 1400 floats of gx per block per step
#define SLAB_BYTES (SLAB * 4) // 5600

typedef unsigned long long ull;

// Precomputed bias-folded x-gates for layer 1: [t][b][g]. Padded for the
// boundary block's over-read (rows 1024..1028 are computed but never output).
__device__ float g_gx[(size_t)T_ * B_ * G_ + 2048];

// ---- f32x2 packed helpers (sm_103a FFMA2) ----
__device__ __forceinline__ void fma2(ull& acc, ull a, ull b) {
    asm("fma.rn.f32x2 %0, %1, %2, %0;" : "+l"(acc) : "l"(a), "l"(b));
}
__device__ __forceinline__ ull pk2(float x, float y) {
    ull r;
    asm("mov.b64 %0, {%1, %2};" : "=l"(r) : "f"(x), "f"(y));
    return r;
}
__device__ __forceinline__ float rsum(ull v) {
    float2 r;
    asm("mov.b64 {%0, %1}, %2;" : "=f"(r.x), "=f"(r.y) : "l"(v));
    return r.x + r.y;
}
__device__ __forceinline__ float sigf(float x) {
    return 1.0f / (1.0f + __expf(-x));
}
__device__ __forceinline__ float tanh_f(float x) {
    return 2.0f / (1.0f + __expf(-2.0f * x)) - 1.0f;
}

__device__ __forceinline__ uint32_t s2u(const void* p) {
    uint32_t a;
    asm("{ .reg .u64 t; cvta.to.shared.u64 t, %1; cvt.u32.u64 %0, t; }"
        : "=r"(a) : "l"(p));
    return a;
}
#define MBINIT(a, c) \
    asm volatile("mbarrier.init.shared.b64 [%0], %1;" :: "r"(a), "r"(c) : "memory")
#define MBEXPECT(a, n) \
    asm volatile("mbarrier.arrive.expect_tx.shared.b64 _, [%0], %1;" :: "r"(a), "r"(n) : "memory")
#define BULKCP(dst, src, n, mb) \
    asm volatile("cp.async.bulk.shared::cta.global.mbarrier::complete_tx::bytes [%0], [%1], %2, [%3];" \
                 :: "r"(dst), "l"(src), "r"(n), "r"(mb) : "memory")
__device__ __forceinline__ void mbwait(uint32_t mb, uint32_t parity) {
    uint32_t done;
    asm volatile(
        "{\n\t.reg .pred p;\n\t"
        "mbarrier.try_wait.parity.acquire.cta.shared::cta.b64 p, [%1], %2;\n\t"
        "selp.b32 %0, 1, 0, p;\n\t}"
        : "=r"(done) : "r"(mb), "r"(parity) : "memory");
    if (!done) {
        asm volatile(
            "{\n\t.reg .pred P1;\n\t"
            "W_%=:\n\t"
            "mbarrier.try_wait.parity.acquire.cta.shared::cta.b64 P1, [%0], %1, 0x989680;\n\t"
            "@P1 bra.uni D_%=;\n\t"
            "bra.uni W_%=;\n\t"
            "D_%=:\n\t}"
            :: "r"(mb), "r"(parity) : "memory");
    }
}

// ============================================================================
// Kernel 1: precompute gx[t][b][g] = b_ih0[g] + b_hh0[g] + x[b,t,:] . w_ih0[g,:]
// ============================================================================
#define TT 64
__global__ __launch_bounds__(256, 4)
void xgate_kernel(const float* __restrict__ x,
                  const float* __restrict__ w_ih0,
                  const float* __restrict__ b_ih0,
                  const float* __restrict__ b_hh0) {
    __shared__ __align__(16) float xs[TT][I_];   // 1024 floats
    const int b   = blockIdx.y;
    const int t0  = blockIdx.x * TT;
    const int tid = threadIdx.x;

    // x[b][t0..t0+TT)[0..16) is contiguous: 256 float4
    const float4* src = (const float4*)(x + ((size_t)b * T_ + t0) * I_);
    ((float4*)xs)[tid] = src[tid];
    __syncthreads();

    if (tid < G_) {
        ull w[8];
        #pragma unroll
        for (int k2 = 0; k2 < 8; k2++)
            w[k2] = pk2(__ldg(&w_ih0[tid * I_ + 2 * k2]),
                        __ldg(&w_ih0[tid * I_ + 2 * k2 + 1]));
        const float bias = __ldg(&b_ih0[tid]) + __ldg(&b_hh0[tid]);
        for (int tt = 0; tt < TT; tt++) {
            ull acc = pk2(bias, 0.0f);
            #pragma unroll
            for (int q = 0; q < 4; q++) {
                const ulonglong2 v = *(const ulonglong2*)&xs[tt][4 * q];
                fma2(acc, w[2 * q],     v.x);
                fma2(acc, w[2 * q + 1], v.y);
            }
            g_gx[((size_t)(t0 + tt) * B_ + b) * G_ + tid] = rsum(acc);
        }
    }
}

// ============================================================================
// Kernel 2: fused 2-layer LSTM recurrence + FC head.
// Pipelined: iter it does L1 step it (gx[it], h1_{it-1}) and L2 step it-1.
// 3 gate groups of 7 warps each: G0: h1.Whh0 ; G1: h1.Wih1 ; G2: h2.Whh1.
// gx slab double-buffered in shared via cp.async.bulk + mbarrier.
// ============================================================================
__global__ __launch_bounds__(NTH, 1)
void fused_lstm_kernel(const float* __restrict__ w_hh0,  // [G, H]
                       const float* __restrict__ w_ih1,  // [G, H]
                       const float* __restrict__ w_hh1,  // [G, H]
                       const float* __restrict__ b_ih1,
                       const float* __restrict__ b_hh1,
                       const float* __restrict__ fc1_w,  // [FC, H]
                       const float* __restrict__ fc1_b,
                       const float* __restrict__ fc2_w,  // [1, FC]
                       const float* __restrict__ fc2_b,
                       float* __restrict__ out)          // [B, 1]
{
    __shared__ __align__(16) float hx[2][NB][52];   // [0]=h1, [1]=h2 (padded)
    __shared__ __align__(16) float gxs[2][SLAB];    // gx slab double buffer
    __shared__ float gl1[NB][G_];                   // L1 gates (full)
    __shared__ float p1[NB][G_];                    // L2 partial (h1 part)
    __shared__ float p2[NB][G_];                    // L2 partial (h2 part)
    __shared__ __align__(8) ull mbar[2];

    const int tid  = threadIdx.x;
    const int row0 = blockIdx.x * NB;
    const int gidx = tid / 224;            // group 0/1/2
    const int g    = tid - gidx * 224;     // gate index if < 200
    const bool isG = (g < G_);

    const uint32_t mb0 = s2u(&mbar[0]);
    const uint32_t mb1 = s2u(&mbar[1]);
    const uint32_t gx0 = s2u(&gxs[0][0]);
    const uint32_t gx1 = s2u(&gxs[1][0]);

    // ---- zero h buffers (pads must stay 0), init mbarriers ----
    for (int i = tid; i < 2 * NB * 52; i += NTH) ((float*)hx)[i] = 0.0f;
    if (tid == 0) { MBINIT(mb0, 1); MBINIT(mb1, 1); }
    __syncthreads();

    // preload gx slab for t=0 into slot 0
    if (tid == 0) {
        MBEXPECT(mb0, SLAB_BYTES);
        BULKCP(gx0, (const void*)(g_gx + (size_t)row0 * G_), SLAB_BYTES, mb0);
    }

    // ---- weights: one matrix per group, 26 f32x2 chunks each ----
    ull w[26];
    float bias2 = 0.0f;
    if (isG) {
        const float* wm = (gidx == 0) ? w_hh0 : (gidx == 1) ? w_ih1 : w_hh1;
        #pragma unroll
        for (int k2 = 0; k2 < 26; k2++) {
            float a0 = (2 * k2     < H_) ? __ldg(&wm[g * H_ + 2 * k2])     : 0.0f;
            float a1 = (2 * k2 + 1 < H_) ? __ldg(&wm[g * H_ + 2 * k2 + 1]) : 0.0f;
            w[k2] = pk2(a0, a1);
        }
        if (gidx == 1) bias2 = __ldg(&b_ih1[g]) + __ldg(&b_hh1[g]);
    }

    // combine state: threads 224..671 own cells (tid-224) and (tid-224)+448
    float c_st[2] = {0.0f, 0.0f};

    int ph0 = 0, ph1 = 0;
    for (int it = 0; it <= T_; it++) {
        const int buf = it & 1;

        // producer: start fill of the other slot with gx[min(it+1, T-1)]
        if (tid == 0) {
            const int tn = (it + 1 < T_) ? (it + 1) : (T_ - 1);
            const uint32_t mbn = buf ? mb0 : mb1;
            const uint32_t gxn = buf ? gx0 : gx1;
            MBEXPECT(mbn, SLAB_BYTES);
            BULKCP(gxn, (const void*)(g_gx + ((size_t)tn * B_ + row0) * G_),
                   SLAB_BYTES, mbn);
        }

        // ---- gate phase ----
        if (isG) {
            if (gidx == 0) {
                // wait for this iter's gx slab
                mbwait(buf ? mb1 : mb0, buf ? ph1 : ph0);
                if (buf) ph1 ^= 1; else ph0 ^= 1;
                ull a[NB];
                #pragma unroll
                for (int r = 0; r < NB; r++)
                    a[r] = pk2(gxs[buf][r * G_ + g], 0.0f);
                #pragma unroll
                for (int q = 0; q < 13; q++) {
                    #pragma unroll
                    for (int r = 0; r < NB; r++) {
                        const ulonglong2 v = *(const ulonglong2*)&hx[0][r][4 * q];
                        fma2(a[r], w[2 * q],     v.x);
                        fma2(a[r], w[2 * q + 1], v.y);
                    }
                }
                #pragma unroll
                for (int r = 0; r < NB; r++) gl1[r][g] = rsum(a[r]);
            } else if (gidx == 1) {
                ull a[NB];
                #pragma unroll
                for (int r = 0; r < NB; r++) a[r] = pk2(bias2, 0.0f);
                #pragma unroll
                for (int q = 0; q < 13; q++) {
                    #pragma unroll
                    for (int r = 0; r < NB; r++) {
                        const ulonglong2 v = *(const ulonglong2*)&hx[0][r][4 * q];
                        fma2(a[r], w[2 * q],     v.x);
                        fma2(a[r], w[2 * q + 1], v.y);
                    }
                }
                #pragma unroll
                for (int r = 0; r < NB; r++) p1[r][g] = rsum(a[r]);
            } else {
                ull a[NB];
                #pragma unroll
                for (int r = 0; r < NB; r++) a[r] = 0ull;
                #pragma unroll
                for (int q = 0; q < 13; q++) {
                    #pragma unroll
                    for (int r = 0; r < NB; r++) {
                        const ulonglong2 v = *(const ulonglong2*)&hx[1][r][4 * q];
                        fma2(a[r], w[2 * q],     v.x);
                        fma2(a[r], w[2 * q + 1], v.y);
                    }
                }
                #pragma unroll
                for (int r = 0; r < NB; r++) p2[r][g] = rsum(a[r]);
            }
        }
        __syncthreads();

        // ---- combine (threads 224..671, up to 2 cells; gate order i,f,g,o) ----
        if (tid >= 224) {
            const int cid = tid - 224;
            #pragma unroll
            for (int k = 0; k < 2; k++) {
                const int cell = cid + k * 448;
                if (cell < NCELL) {
                    const bool l2 = (cell >= NC1);
                    const int rem = l2 ? cell - NC1 : cell;
                    const int r = rem / H_;
                    const int j = rem - r * H_;
                    const bool act = l2 ? (it >= 1) : (it < T_);
                    if (act) {
                        float gi, gf, gg, go;
                        if (l2) {
                            gi = p1[r][j]           + p2[r][j];
                            gf = p1[r][H_ + j]      + p2[r][H_ + j];
                            gg = p1[r][2 * H_ + j]  + p2[r][2 * H_ + j];
                            go = p1[r][3 * H_ + j]  + p2[r][3 * H_ + j];
                        } else {
                            gi = gl1[r][j];
                            gf = gl1[r][H_ + j];
                            gg = gl1[r][2 * H_ + j];
                            go = gl1[r][3 * H_ + j];
                        }
                        const float ig = sigf(gi);
                        const float fg = sigf(gf);
                        const float gv = tanh_f(gg);
                        const float og = sigf(go);
                        c_st[k] = fg * c_st[k] + ig * gv;
                        hx[l2 ? 1 : 0][r][j] = og * tanh_f(c_st[k]);
                    }
                }
            }
        }
        __syncthreads();
    }

    // ---- FC head: warps 0-6 each handle one batch row, shfl reduction ----
    const int wid  = tid / 32;
    const int lane = tid - wid * 32;
    if (wid < NB) {
        const int row = row0 + wid;
        if (row < B_) {
            float s = 0.0f;
            #pragma unroll
            for (int uu = 0; uu < 2; uu++) {
                const int u = lane + uu * 32;
                float a = __ldg(&fc1_b[u]);
                #pragma unroll
                for (int k = 0; k < H_; k++)
                    a += __ldg(&fc1_w[u * H_ + k]) * hx[1][wid][k];
                a = fmaxf(a, 0.0f);
                s += a * __ldg(&fc2_w[u]);
            }
            #pragma unroll
            for (int off = 16; off > 0; off >>= 1)
                s += __shfl_down_sync(0xffffffffu, s, off);
            if (lane == 0) out[row] = s + __ldg(&fc2_b[0]);
        }
    }
}

extern "C" void kernel_launch(void* const* d_in, const int* in_sizes, int n_in,
                              void* d_out, int out_size) {
    const float* x     = (const float*)d_in[0];
    const float* w_ih0 = (const float*)d_in[1];
    const float* w_hh0 = (const float*)d_in[2];
    const float* b_ih0 = (const float*)d_in[3];
    const float* b_hh0 = (const float*)d_in[4];
    const float* w_ih1 = (const float*)d_in[5];
    const float* w_hh1 = (const float*)d_in[6];
    const float* b_ih1 = (const float*)d_in[7];
    const float* b_hh1 = (const float*)d_in[8];
    const float* fc1_w = (const float*)d_in[9];
    const float* fc1_b = (const float*)d_in[10];
    const float* fc2_w = (const float*)d_in[11];
    const float* fc2_b = (const float*)d_in[12];
    float* out = (float*)d_out;

    dim3 xg_grid(T_ / TT, B_);
    xgate_kernel<<<xg_grid, 256>>>(x, w_ih0, b_ih0, b_hh0);

    const int grid = (B_ + NB - 1) / NB;   // 147
    fused_lstm_kernel<<<grid, NTH>>>(
        w_hh0, w_ih1, w_hh1, b_ih1, b_hh1,
        fc1_w, fc1_b, fc2_w, fc2_b, out);
}

// round 6
// speedup vs baseline: 1.2027x; 1.0873x over previous
#include <cuda_runtime.h>
#include <cstdint>

// Problem constants
#define B_   1024
#define T_   512
#define I_   16
#define H_   50
#define G_   200      // 4*H
#define FCD  64
#define NB   7        // rows per block -> grid 147, single wave
#define NTH  672      // 21 warps: 3 groups x 7 warps (200 gate threads each)
#define NC1  (NB * H_)        // 350
#define NCELL (2 * NB * H_)   // 700
#define SLAB (NB * G_)        // 1400 floats of gx per block per step
#define SLAB_BYTES (SLAB * 4) // 5600

typedef unsigned long long ull;

// Precomputed bias-folded x-gates for layer 1: [t][b][g]. Padding covers the
// boundary block's over-read (rows 1024..1028, zero -> finite garbage, unused).
__device__ float g_gx[(size_t)T_ * B_ * G_ + 2048];

// ---- f32x2 packed helpers (sm_103a FFMA2) ----
__device__ __forceinline__ void fma2(ull& acc, ull a, ull b) {
    asm("fma.rn.f32x2 %0, %1, %2, %0;" : "+l"(acc) : "l"(a), "l"(b));
}
__device__ __forceinline__ ull pk2(float x, float y) {
    ull r;
    asm("mov.b64 %0, {%1, %2};" : "=l"(r) : "f"(x), "f"(y));
    return r;
}
__device__ __forceinline__ float rsum(ull v) {
    float2 r;
    asm("mov.b64 {%0, %1}, %2;" : "=f"(r.x), "=f"(r.y) : "l"(v));
    return r.x + r.y;
}

// ---- fast activations: single-MUFU ex2 / rcp (no Newton-refined division) ----
__device__ __forceinline__ float fex2(float x) {
    float r;
    asm("ex2.approx.f32 %0, %1;" : "=f"(r) : "f"(x));
    return r;
}
__device__ __forceinline__ float frcp(float x) {
    float r;
    asm("rcp.approx.f32 %0, %1;" : "=f"(r) : "f"(x));
    return r;
}
#define LOG2E  1.4426950408889634f
__device__ __forceinline__ float sigf(float x) {
    return frcp(1.0f + fex2(-LOG2E * x));
}
__device__ __forceinline__ float tanh_f(float x) {
    return 2.0f * frcp(1.0f + fex2(-2.0f * LOG2E * x)) - 1.0f;
}

__device__ __forceinline__ uint32_t s2u(const void* p) {
    uint32_t a;
    asm("{ .reg .u64 t; cvta.to.shared.u64 t, %1; cvt.u32.u64 %0, t; }"
        : "=r"(a) : "l"(p));
    return a;
}
#define MBINIT(a, c) \
    asm volatile("mbarrier.init.shared.b64 [%0], %1;" :: "r"(a), "r"(c) : "memory")
#define MBEXPECT(a, n) \
    asm volatile("mbarrier.arrive.expect_tx.shared.b64 _, [%0], %1;" :: "r"(a), "r"(n) : "memory")
#define BULKCP(dst, src, n, mb) \
    asm volatile("cp.async.bulk.shared::cta.global.mbarrier::complete_tx::bytes [%0], [%1], %2, [%3];" \
                 :: "r"(dst), "l"(src), "r"(n), "r"(mb) : "memory")
__device__ __forceinline__ void mbwait(uint32_t mb, uint32_t parity) {
    uint32_t done;
    asm volatile(
        "{\n\t.reg .pred p;\n\t"
        "mbarrier.try_wait.parity.acquire.cta.shared::cta.b64 p, [%1], %2;\n\t"
        "selp.b32 %0, 1, 0, p;\n\t}"
        : "=r"(done) : "r"(mb), "r"(parity) : "memory");
    if (!done) {
        asm volatile(
            "{\n\t.reg .pred P1;\n\t"
            "W_%=:\n\t"
            "mbarrier.try_wait.parity.acquire.cta.shared::cta.b64 P1, [%0], %1, 0x989680;\n\t"
            "@P1 bra.uni D_%=;\n\t"
            "bra.uni W_%=;\n\t"
            "D_%=:\n\t}"
            :: "r"(mb), "r"(parity) : "memory");
    }
}

// ============================================================================
// Kernel 1: gx[t][b][g] = b_ih0[g] + b_hh0[g] + x[b,t,:] . w_ih0[g,:]
// ============================================================================
#define TT 128
__global__ __launch_bounds__(256, 4)
void xgate_kernel(const float* __restrict__ x,
                  const float* __restrict__ w_ih0,
                  const float* __restrict__ b_ih0,
                  const float* __restrict__ b_hh0) {
    __shared__ __align__(16) float xs[TT][I_];   // 8 KB
    const int b   = blockIdx.y;
    const int t0  = blockIdx.x * TT;
    const int tid = threadIdx.x;

    // x[b][t0..t0+TT)[0..16) contiguous: TT*4 float4 = 512
    const float4* src = (const float4*)(x + ((size_t)b * T_ + t0) * I_);
    ((float4*)xs)[tid]       = src[tid];
    ((float4*)xs)[tid + 256] = src[tid + 256];
    __syncthreads();

    if (tid < G_) {
        ull w[8];
        #pragma unroll
        for (int k2 = 0; k2 < 8; k2++)
            w[k2] = pk2(__ldg(&w_ih0[tid * I_ + 2 * k2]),
                        __ldg(&w_ih0[tid * I_ + 2 * k2 + 1]));
        const float bias = __ldg(&b_ih0[tid]) + __ldg(&b_hh0[tid]);
        for (int tt = 0; tt < TT; tt++) {
            ull acc = pk2(bias, 0.0f);
            #pragma unroll
            for (int q = 0; q < 4; q++) {
                const ulonglong2 v = *(const ulonglong2*)&xs[tt][4 * q];
                fma2(acc, w[2 * q],     v.x);
                fma2(acc, w[2 * q + 1], v.y);
            }
            g_gx[((size_t)(t0 + tt) * B_ + b) * G_ + tid] = rsum(acc);
        }
    }
}

// ============================================================================
// Kernel 2: fused 2-layer LSTM recurrence + FC head.
// iter it: L1 step it (gx[it], h1_{it-1});  L2 step it-1 (h1_{it-1}, h2_{it-2})
// 3 gate groups of 7 warps: G0: gx + h1.Whh0 ; G1: h1.Wih1 ; G2: h2.Whh1.
// Combine spread across ALL 672 threads. gx double-buffered via cp.async.bulk.
// ============================================================================
__global__ __launch_bounds__(NTH, 1)
void fused_lstm_kernel(const float* __restrict__ w_hh0,  // [G, H]
                       const float* __restrict__ w_ih1,  // [G, H]
                       const float* __restrict__ w_hh1,  // [G, H]
                       const float* __restrict__ b_ih1,
                       const float* __restrict__ b_hh1,
                       const float* __restrict__ fc1_w,  // [FC, H]
                       const float* __restrict__ fc1_b,
                       const float* __restrict__ fc2_w,  // [1, FC]
                       const float* __restrict__ fc2_b,
                       float* __restrict__ out)          // [B, 1]
{
    __shared__ __align__(16) float hx[2][NB][52];   // [0]=h1, [1]=h2 (padded)
    __shared__ __align__(16) float gxs[2][SLAB];    // gx slab double buffer
    __shared__ float gl1[NB][G_];                   // L1 gates (full)
    __shared__ float p1[NB][G_];                    // L2 partial (h1 part)
    __shared__ float p2[NB][G_];                    // L2 partial (h2 part)
    __shared__ __align__(8) ull mbar[2];

    const int tid  = threadIdx.x;
    const int row0 = blockIdx.x * NB;
    const int gidx = tid / 224;            // group 0/1/2
    const int g    = tid - gidx * 224;     // gate index if < 200
    const bool isG = (g < G_);

    const uint32_t mb0 = s2u(&mbar[0]);
    const uint32_t mb1 = s2u(&mbar[1]);
    const uint32_t gx0 = s2u(&gxs[0][0]);
    const uint32_t gx1 = s2u(&gxs[1][0]);

    // ---- zero h buffers (pads must stay 0), init mbarriers ----
    for (int i = tid; i < 2 * NB * 52; i += NTH) ((float*)hx)[i] = 0.0f;
    if (tid == 0) { MBINIT(mb0, 1); MBINIT(mb1, 1); }
    __syncthreads();

    // preload gx slab for t=0 into slot 0
    if (tid == 0) {
        MBEXPECT(mb0, SLAB_BYTES);
        BULKCP(gx0, (const void*)(g_gx + (size_t)row0 * G_), SLAB_BYTES, mb0);
    }

    // ---- weights: one matrix per group, 26 f32x2 chunks each ----
    ull w[26];
    float bias2 = 0.0f;
    if (isG) {
        const float* wm = (gidx == 0) ? w_hh0 : (gidx == 1) ? w_ih1 : w_hh1;
        #pragma unroll
        for (int k2 = 0; k2 < 26; k2++) {
            float a0 = (2 * k2     < H_) ? __ldg(&wm[g * H_ + 2 * k2])     : 0.0f;
            float a1 = (2 * k2 + 1 < H_) ? __ldg(&wm[g * H_ + 2 * k2 + 1]) : 0.0f;
            w[k2] = pk2(a0, a1);
        }
        if (gidx == 1) bias2 = __ldg(&b_ih1[g]) + __ldg(&b_hh1[g]);
    }

    // ---- combine ownership: ALL threads. cell tid, plus cell tid+672 for tid<28 ----
    float c_st[2] = {0.0f, 0.0f};
    int   coff[2], hoff[2];
    bool  cval[2], cl2[2];
    #pragma unroll
    for (int k = 0; k < 2; k++) {
        const int cell = tid + k * NTH;
        cval[k] = (cell < NCELL);
        const int c = cval[k] ? cell : 0;
        cl2[k] = (c >= NC1);
        const int rem = cl2[k] ? c - NC1 : c;
        const int r = rem / H_;
        const int j = rem - r * H_;
        coff[k] = r * G_ + j;
        hoff[k] = (cl2[k] ? NB * 52 : 0) + r * 52 + j;
    }

    int ph0 = 0, ph1 = 0;
    for (int it = 0; it <= T_; it++) {
        const int buf = it & 1;

        // producer: start fill of the other slot with gx[it+1] (skip past end)
        if (tid == 0 && it < T_) {
            const int tn = (it + 1 < T_) ? (it + 1) : (T_ - 1);
            const uint32_t mbn = buf ? mb0 : mb1;
            const uint32_t gxn = buf ? gx0 : gx1;
            MBEXPECT(mbn, SLAB_BYTES);
            BULKCP(gxn, (const void*)(g_gx + ((size_t)tn * B_ + row0) * G_),
                   SLAB_BYTES, mbn);
        }

        // ---- gate phase ----
        if (isG) {
            if (gidx == 0) {
                mbwait(buf ? mb1 : mb0, buf ? ph1 : ph0);
                if (buf) ph1 ^= 1; else ph0 ^= 1;
                ull a[NB];
                #pragma unroll
                for (int r = 0; r < NB; r++)
                    a[r] = pk2(gxs[buf][r * G_ + g], 0.0f);
                #pragma unroll
                for (int q = 0; q < 13; q++) {
                    #pragma unroll
                    for (int r = 0; r < NB; r++) {
                        const ulonglong2 v = *(const ulonglong2*)&hx[0][r][4 * q];
                        fma2(a[r], w[2 * q],     v.x);
                        fma2(a[r], w[2 * q + 1], v.y);
                    }
                }
                #pragma unroll
                for (int r = 0; r < NB; r++) gl1[r][g] = rsum(a[r]);
            } else if (gidx == 1) {
                ull a[NB];
                #pragma unroll
                for (int r = 0; r < NB; r++) a[r] = pk2(bias2, 0.0f);
                #pragma unroll
                for (int q = 0; q < 13; q++) {
                    #pragma unroll
                    for (int r = 0; r < NB; r++) {
                        const ulonglong2 v = *(const ulonglong2*)&hx[0][r][4 * q];
                        fma2(a[r], w[2 * q],     v.x);
                        fma2(a[r], w[2 * q + 1], v.y);
                    }
                }
                #pragma unroll
                for (int r = 0; r < NB; r++) p1[r][g] = rsum(a[r]);
            } else {
                ull a[NB];
                #pragma unroll
                for (int r = 0; r < NB; r++) a[r] = 0ull;
                #pragma unroll
                for (int q = 0; q < 13; q++) {
                    #pragma unroll
                    for (int r = 0; r < NB; r++) {
                        const ulonglong2 v = *(const ulonglong2*)&hx[1][r][4 * q];
                        fma2(a[r], w[2 * q],     v.x);
                        fma2(a[r], w[2 * q + 1], v.y);
                    }
                }
                #pragma unroll
                for (int r = 0; r < NB; r++) p2[r][g] = rsum(a[r]);
            }
        }
        __syncthreads();

        // ---- combine: all threads, 1-2 cells each (gate order i, f, g, o) ----
        #pragma unroll
        for (int k = 0; k < 2; k++) {
            if (cval[k]) {
                const bool act = cl2[k] ? (it >= 1) : (it < T_);
                if (act) {
                    const int o = coff[k];
                    float gi, gf, gg, go;
                    if (cl2[k]) {
                        const float* q1 = &p1[0][0];
                        const float* q2 = &p2[0][0];
                        gi = q1[o]           + q2[o];
                        gf = q1[o + H_]      + q2[o + H_];
                        gg = q1[o + 2 * H_]  + q2[o + 2 * H_];
                        go = q1[o + 3 * H_]  + q2[o + 3 * H_];
                    } else {
                        const float* q0 = &gl1[0][0];
                        gi = q0[o];
                        gf = q0[o + H_];
                        gg = q0[o + 2 * H_];
                        go = q0[o + 3 * H_];
                    }
                    const float ig = sigf(gi);
                    const float fg = sigf(gf);
                    const float gv = tanh_f(gg);
                    const float og = sigf(go);
                    c_st[k] = fg * c_st[k] + ig * gv;
                    ((float*)hx)[hoff[k]] = og * tanh_f(c_st[k]);
                }
            }
        }
        __syncthreads();
    }

    // ---- FC head: warps 0-6 each handle one batch row, shfl reduction ----
    const int wid  = tid / 32;
    const int lane = tid - wid * 32;
    if (wid < NB) {
        const int row = row0 + wid;
        if (row < B_) {
            float s = 0.0f;
            #pragma unroll
            for (int uu = 0; uu < 2; uu++) {
                const int u = lane + uu * 32;
                float a = __ldg(&fc1_b[u]);
                #pragma unroll
                for (int k = 0; k < H_; k++)
                    a += __ldg(&fc1_w[u * H_ + k]) * hx[1][wid][k];
                a = fmaxf(a, 0.0f);
                s += a * __ldg(&fc2_w[u]);
            }
            #pragma unroll
            for (int off = 16; off > 0; off >>= 1)
                s += __shfl_down_sync(0xffffffffu, s, off);
            if (lane == 0) out[row] = s + __ldg(&fc2_b[0]);
        }
    }
}

extern "C" void kernel_launch(void* const* d_in, const int* in_sizes, int n_in,
                              void* d_out, int out_size) {
    const float* x     = (const float*)d_in[0];
    const float* w_ih0 = (const float*)d_in[1];
    const float* w_hh0 = (const float*)d_in[2];
    const float* b_ih0 = (const float*)d_in[3];
    const float* b_hh0 = (const float*)d_in[4];
    const float* w_ih1 = (const float*)d_in[5];
    const float* w_hh1 = (const float*)d_in[6];
    const float* b_ih1 = (const float*)d_in[7];
    const float* b_hh1 = (const float*)d_in[8];
    const float* fc1_w = (const float*)d_in[9];
    const float* fc1_b = (const float*)d_in[10];
    const float* fc2_w = (const float*)d_in[11];
    const float* fc2_b = (const float*)d_in[12];
    float* out = (float*)d_out;

    dim3 xg_grid(T_ / TT, B_);
    xgate_kernel<<<xg_grid, 256>>>(x, w_ih0, b_ih0, b_hh0);

    const int grid = (B_ + NB - 1) / NB;   // 147
    fused_lstm_kernel<<<grid, NTH>>>(
        w_hh0, w_ih1, w_hh1, b_ih1, b_hh1,
        fc1_w, fc1_b, fc2_w, fc2_b, out);
}